// round 1
// baseline (speedup 1.0000x reference)
#include <cuda_runtime.h>

// ---------------- problem constants ----------------
#define NNODES 4096          // B*n
#define NBATCH 64
#define NPG    64            // nodes per graph
#define HD     128
#define HD4    32            // HD/4
#define NE     131072        // B*epg edges (before self loops)
#define KK     52            // ceil(0.8*64)
#define NK     3328          // B*KK

#define LEN_X  (NK*HD)                    // 425984
#define OFF_A2 (LEN_X)
#define OFF_B  (OFF_A2 + NK*NK)           // 11501568
#define OFF_P  (OFF_B + NK)               // 11504896

// ---------------- scratch (device globals; no allocation) ----------------
__device__ float g_deg[NNODES];
__device__ float g_dinv[NNODES];
__device__ float g_A[NBATCH*NPG*NPG];     // dense per-batch normalized adjacency (row,col)
__device__ float g_Cnt[NBATCH*NPG*NPG];   // edge multiplicity
__device__ float g_S[NBATCH*NPG*NPG];     // E_g dense per-batch
__device__ float g_tmp[NNODES*HD];
__device__ float g_xq[NNODES*HD];
__device__ float g_qt[NNODES*HD];
__device__ float g_a[2*NNODES*HD];
__device__ float g_h0[2*NNODES*4*HD];
__device__ float g_h1[2*NNODES*2*HD];
__device__ float g_h2[2*NNODES*HD];
__device__ float g_logit[2*NNODES];
__device__ float g_f[2*NNODES];
__device__ float g_agg[NNODES*HD];
__device__ float g_P[2*NNODES*HD];
__device__ float g_xc[NNODES*HD];
__device__ float g_score[NNODES];
__device__ int   g_perm[NK];

__device__ __forceinline__ float lrelu(float v){ return v > 0.f ? v : 0.01f*v; }

// ---------------- setup kernels ----------------
__global__ void k_init(){
    int i = blockIdx.x*blockDim.x + threadIdx.x;
    if (i < NBATCH*NPG*NPG){ g_A[i]=0.f; g_Cnt[i]=0.f; }
    if (i < NNODES) g_deg[i] = 1.0f;     // self-loop weight
}

__global__ void k_deg(const int* __restrict__ col, const float* __restrict__ w){
    int e = blockIdx.x*blockDim.x + threadIdx.x;
    if (e < NE) atomicAdd(&g_deg[col[e]], w[e]);
}

__global__ void k_dinv(){
    int i = blockIdx.x*blockDim.x + threadIdx.x;
    if (i < NNODES) g_dinv[i] = rsqrtf(g_deg[i]);
}

__global__ void k_build(const int* __restrict__ row, const int* __restrict__ col,
                        const float* __restrict__ w){
    int e = blockIdx.x*blockDim.x + threadIdx.x;
    if (e < NE){
        int r = row[e], c = col[e];
        float ew = g_dinv[r]*w[e]*g_dinv[c];
        int b = r >> 6;
        int idx = b*NPG*NPG + (r&63)*NPG + (c&63);
        atomicAdd(&g_A[idx], ew);
        atomicAdd(&g_Cnt[idx], 1.0f);
    } else if (e < NE + NNODES){
        int i = e - NE;
        int b = i >> 6, l = i & 63;
        int idx = b*NPG*NPG + l*NPG + l;
        atomicAdd(&g_A[idx], g_dinv[i]*g_dinv[i]);
        atomicAdd(&g_Cnt[idx], 1.0f);
    }
}

__global__ void k_qt(const float4* __restrict__ tx4){
    int i = blockIdx.x*blockDim.x + threadIdx.x;   // < NNODES*HD4
    int node = i >> 5, f4 = i & 31;
    ((float4*)g_qt)[i] = tx4[(node>>6)*HD4 + f4];
}

// hop: out[c] = sum_r A[r][c] * v[r]  (per-batch dense)
__global__ void k_hop(const float4* __restrict__ vin, float4* __restrict__ vout){
    int b = blockIdx.x, t = threadIdx.x;
    __shared__ float sA[NPG*NPG];
    for (int i=t; i<NPG*NPG; i+=256) sA[i] = g_A[b*NPG*NPG+i];
    __syncthreads();
    int tx = t & 31, ty = t >> 5;
    for (int cc=0; cc<8; cc++){
        int c = ty*8+cc;
        float4 acc = make_float4(0.f,0.f,0.f,0.f);
        for (int r=0; r<NPG; r++){
            float a = sA[r*NPG+c];
            float4 v = vin[(b*NPG+r)*HD4 + tx];
            acc.x += a*v.x; acc.y += a*v.y; acc.z += a*v.z; acc.w += a*v.w;
        }
        vout[(b*NPG+c)*HD4 + tx] = acc;
    }
}

// ---------------- generic z-batched SGEMM: C = act(A @ B) ----------------
// A: MxK row-major, B: KxN row-major, C: MxN. 64x64 tile, 4x4 per thread.
__global__ void k_sgemm(const float* __restrict__ A, const float* __restrict__ B,
                        float* __restrict__ C, int M, int Nn, int K,
                        long long sA, long long sB, long long sC, int act)
{
    A += (long long)blockIdx.z * sA;
    B += (long long)blockIdx.z * sB;
    C += (long long)blockIdx.z * sC;
    __shared__ float As[16*64];
    __shared__ float Bs[16*64];
    int t = threadIdx.x;
    int tx = t & 15, ty = t >> 4;
    int rowBase = blockIdx.y*64, colBase = blockIdx.x*64;
    int ar = t >> 2, ak = t & 3;
    int bk = t >> 4, bc = t & 15;
    float acc[4][4] = {};
    for (int k0=0; k0<K; k0+=16){
        float4 av = *(const float4*)(A + (size_t)(rowBase+ar)*K + k0 + ak*4);
        As[(ak*4+0)*64+ar]=av.x;
        As[(ak*4+1)*64+ar]=av.y;
        As[(ak*4+2)*64+ar]=av.z;
        As[(ak*4+3)*64+ar]=av.w;
        *(float4*)(Bs + bk*64 + bc*4) = *(const float4*)(B + (size_t)(k0+bk)*Nn + colBase + bc*4);
        __syncthreads();
#pragma unroll
        for (int kk=0; kk<16; kk++){
            float4 a  = *(const float4*)(As + kk*64 + ty*4);
            float4 bq = *(const float4*)(Bs + kk*64 + tx*4);
            acc[0][0]+=a.x*bq.x; acc[0][1]+=a.x*bq.y; acc[0][2]+=a.x*bq.z; acc[0][3]+=a.x*bq.w;
            acc[1][0]+=a.y*bq.x; acc[1][1]+=a.y*bq.y; acc[1][2]+=a.y*bq.z; acc[1][3]+=a.y*bq.w;
            acc[2][0]+=a.z*bq.x; acc[2][1]+=a.z*bq.y; acc[2][2]+=a.z*bq.z; acc[2][3]+=a.z*bq.w;
            acc[3][0]+=a.w*bq.x; acc[3][1]+=a.w*bq.y; acc[3][2]+=a.w*bq.z; acc[3][3]+=a.w*bq.w;
        }
        __syncthreads();
    }
#pragma unroll
    for (int i=0; i<4; i++){
        float4 v = make_float4(acc[i][0], acc[i][1], acc[i][2], acc[i][3]);
        if (act){ v.x=lrelu(v.x); v.y=lrelu(v.y); v.z=lrelu(v.z); v.w=lrelu(v.w); }
        *(float4*)(C + (size_t)(rowBase+ty*4+i)*Nn + colBase + tx*4) = v;
    }
}

// ---------------- attention helpers ----------------
__global__ void k_h0(const float* __restrict__ q0, const float* __restrict__ q1){
    int i = blockIdx.x*blockDim.x + threadIdx.x;     // < 2*NNODES*HD
    int z = i / (NNODES*HD);
    int rem = i - z*(NNODES*HD);
    int node = rem >> 7, f = rem & 127;
    float a = g_a[i];
    float qv = (z ? q1 : q0)[rem];
    float* h = &g_h0[((size_t)z*NNODES + node)*512];
    h[f] = a; h[128+f] = qv; h[256+f] = a - qv; h[384+f] = a*qv;
}

__global__ void k_w3(const float* __restrict__ W3, int base){
    int gt = blockIdx.x*blockDim.x + threadIdx.x;
    int warp = gt >> 5, lane = gt & 31;
    if (warp >= 2*NNODES) return;
    int z = warp >> 12;
    const float* w = W3 + (size_t)(base+z)*HD;
    const float* h = g_h2 + (size_t)warp*HD;
    float s = 0.f;
#pragma unroll
    for (int k=0; k<4; k++) s += h[lane+32*k]*w[lane+32*k];
    for (int o=16; o; o>>=1) s += __shfl_xor_sync(0xffffffffu, s, o);
    if (lane == 0) g_logit[warp] = lrelu(s);
}

__global__ void k_softmax64(const float* __restrict__ in, float* __restrict__ out){
    __shared__ float red[64];
    int b = blockIdx.x, t = threadIdx.x;
    float v = in[b*64+t];
    red[t] = v; __syncthreads();
    for (int o=32; o>0; o>>=1){ if (t<o) red[t] = fmaxf(red[t], red[t+o]); __syncthreads(); }
    float m = red[0];
    __syncthreads();
    float e = expf(v - m);
    red[t] = e; __syncthreads();
    for (int o=32; o>0; o>>=1){ if (t<o) red[t] += red[t+o]; __syncthreads(); }
    out[b*64+t] = e / red[0];
}

// ---------------- edge softmax + S + agg (per-batch dense) ----------------
__global__ void k_edge(const float* __restrict__ x){
    int b = blockIdx.x, t = threadIdx.x;
    __shared__ float sC[NPG*NPG];
    __shared__ float sL[NPG*NPG];
    __shared__ float sf1[NPG], sf2[NPG], sm[NPG], sden[NPG];
    for (int i=t; i<NPG*NPG; i+=256) sC[i] = g_Cnt[b*NPG*NPG+i];
    if (t < NPG){ sf1[t] = g_f[b*NPG+t]; sf2[t] = g_f[NNODES + b*NPG+t]; }
    __syncthreads();
    for (int i=t; i<NPG*NPG; i+=256){
        int r = i>>6, c = i&63;
        sL[i] = (sC[i] > 0.f) ? lrelu(sf1[c] + sf2[r]) : -1e30f;
    }
    __syncthreads();
    if (t < NPG){
        float m = -1e30f;
        for (int r=0; r<NPG; r++) m = fmaxf(m, sL[r*NPG+t]);
        float den = 0.f;
        for (int r=0; r<NPG; r++){
            float cc = sC[r*NPG+t];
            if (cc > 0.f) den += cc*expf(sL[r*NPG+t]-m);
        }
        sm[t] = m; sden[t] = den;
    }
    __syncthreads();
    for (int i=t; i<NPG*NPG; i+=256){
        int c = i & 63;
        float cc = sC[i];
        float s = (cc > 0.f) ? cc*expf(sL[i]-sm[c])/sden[c] : 0.f;
        sL[i] = s;
        g_S[b*NPG*NPG+i] = s;
    }
    __syncthreads();
    const float4* X4 = (const float4*)x;
    float4* AG4 = (float4*)g_agg;
    int tx = t & 31, ty = t >> 5;
    for (int cc=0; cc<8; cc++){
        int c = ty*8+cc;
        float4 acc = make_float4(0.f,0.f,0.f,0.f);
        for (int r=0; r<NPG; r++){
            float s = sL[r*NPG+c];
            float4 v = X4[(b*NPG+r)*HD4 + tx];
            acc.x += s*v.x; acc.y += s*v.y; acc.z += s*v.z; acc.w += s*v.w;
        }
        AG4[(b*NPG+c)*HD4 + tx] = acc;
    }
}

__global__ void k_xc(const float* __restrict__ x){
    int i = blockIdx.x*blockDim.x + threadIdx.x;
    if (i < NNODES*HD){
        float xv = x[i];
        float v0 = lrelu(xv + g_P[i]);
        float v1 = lrelu(xv + g_P[NNODES*HD + i]);
        g_xc[i] = 0.5f*(v0+v1);
    }
}

__global__ void k_sumpair(){
    int i = blockIdx.x*blockDim.x + threadIdx.x;
    if (i < NNODES) g_logit[i] = g_f[i] + g_f[NNODES+i];
}

// ---------------- top-k (stable, descending) ----------------
__global__ void k_topk(float* __restrict__ out){
    __shared__ float s[64];
    int b = blockIdx.x, t = threadIdx.x;
    s[t] = g_score[b*64+t];
    __syncthreads();
    float v = s[t];
    int rank = 0;
    for (int j=0; j<64; j++){
        float u = s[j];
        rank += (u > v) || (u == v && j < t);
    }
    if (rank < KK){
        int g = b*64+t;
        g_perm[b*KK+rank] = g;
        out[OFF_B + b*KK+rank] = (float)b;
        out[OFF_P + b*KK+rank] = (float)g;
    }
}

__global__ void k_xout(const float* __restrict__ x, float* __restrict__ out){
    int i = blockIdx.x*blockDim.x + threadIdx.x;   // < NK*HD
    int r = i >> 7, f = i & 127;
    int p = g_perm[r];
    out[i] = x[p*HD + f] * g_score[p];
}

// ---------------- A2 block triple-product ----------------
__global__ void k_A2(float* __restrict__ out){
    int b = blockIdx.x, t = threadIdx.x;
    __shared__ float sA[NPG*NPG];
    __shared__ float sS[NPG*NPG];
    __shared__ float sU[NPG*KK];
    __shared__ int   sI[KK];
    for (int i=t; i<NPG*NPG; i+=256){ sA[i] = g_A[b*NPG*NPG+i]; sS[i] = g_S[b*NPG*NPG+i]; }
    if (t < KK) sI[t] = g_perm[b*KK+t] - b*NPG;
    __syncthreads();
    // U[r][j] = sum_c A[r][c] * S[c][pj]
    for (int idx=t; idx<NPG*KK; idx+=256){
        int r = idx / KK, j = idx - r*KK;
        int pj = sI[j];
        float acc = 0.f;
        for (int c=0; c<NPG; c++) acc += sA[r*NPG+c]*sS[c*NPG+pj];
        sU[idx] = acc;
    }
    __syncthreads();
    // V[i][j] = sum_r S[r][pi] * U[r][j]; diag -> 1
    for (int idx=t; idx<KK*KK; idx+=256){
        int i2 = idx / KK, j = idx - i2*KK;
        int pi = sI[i2];
        float acc = 0.f;
        for (int r=0; r<NPG; r++) acc += sS[r*NPG+pi]*sU[r*KK+j];
        float v = (i2 == j) ? 1.0f : acc;
        out[(size_t)OFF_A2 + (size_t)(b*KK+i2)*NK + (b*KK+j)] = v;
    }
}

// ---------------- host-side attention pipeline ----------------
static void launch_attention(int base, const float* kv, const float* q0, const float* q1,
                             const float* Wk, const float* W1, const float* W2, const float* W3,
                             float* p_a, float* p_h0, float* p_h1, float* p_h2,
                             float* p_logit, float* p_f)
{
    k_sgemm<<<dim3(2,64,2),256>>>(kv, Wk + (long long)base*HD*HD, p_a,
                                  NNODES, HD, HD,
                                  0LL, (long long)HD*HD, (long long)NNODES*HD, 0);
    k_h0<<<(2*NNODES*HD)/256,256>>>(q0, q1);
    k_sgemm<<<dim3(4,64,2),256>>>(p_h0, W1 + (long long)base*512*256, p_h1,
                                  NNODES, 256, 512,
                                  (long long)NNODES*512, 512LL*256, (long long)NNODES*256, 1);
    k_sgemm<<<dim3(2,64,2),256>>>(p_h1, W2 + (long long)base*256*128, p_h2,
                                  NNODES, 128, 256,
                                  (long long)NNODES*256, 256LL*128, (long long)NNODES*128, 1);
    k_w3<<<(2*NNODES*32)/256,256>>>(W3, base);
    k_softmax64<<<2*NBATCH,64>>>(p_logit, p_f);
}

extern "C" void kernel_launch(void* const* d_in, const int* in_sizes, int n_in,
                              void* d_out, int out_size)
{
    (void)in_sizes; (void)n_in; (void)out_size;
    const float* x    = (const float*)d_in[0];
    const int*   ei   = (const int*)  d_in[1];
    const float* ew   = (const float*)d_in[2];
    const float* txg  = (const float*)d_in[3];
    const float* Wk   = (const float*)d_in[5];
    const float* W1   = (const float*)d_in[6];
    const float* W2   = (const float*)d_in[7];
    const float* W3   = (const float*)d_in[8];
    const float* linW = (const float*)d_in[9];
    float* out = (float*)d_out;
    const int* row = ei;
    const int* col = ei + NE;

    float *p_tmp,*p_xq,*p_qt,*p_a,*p_h0,*p_h1,*p_h2,*p_logit,*p_f,*p_agg,*p_P,*p_xc,*p_score;
    cudaGetSymbolAddress((void**)&p_tmp,   g_tmp);
    cudaGetSymbolAddress((void**)&p_xq,    g_xq);
    cudaGetSymbolAddress((void**)&p_qt,    g_qt);
    cudaGetSymbolAddress((void**)&p_a,     g_a);
    cudaGetSymbolAddress((void**)&p_h0,    g_h0);
    cudaGetSymbolAddress((void**)&p_h1,    g_h1);
    cudaGetSymbolAddress((void**)&p_h2,    g_h2);
    cudaGetSymbolAddress((void**)&p_logit, g_logit);
    cudaGetSymbolAddress((void**)&p_f,     g_f);
    cudaGetSymbolAddress((void**)&p_agg,   g_agg);
    cudaGetSymbolAddress((void**)&p_P,     g_P);
    cudaGetSymbolAddress((void**)&p_xc,    g_xc);
    cudaGetSymbolAddress((void**)&p_score, g_score);

    // graph setup
    k_init<<<1024,256>>>();
    k_deg<<<NE/256,256>>>(col, ew);
    k_dinv<<<NNODES/256,256>>>();
    k_build<<<(NE+NNODES)/256,256>>>(row, col, ew);
    k_qt<<<(NNODES*HD4)/256,256>>>((const float4*)txg);

    // x_q = hop(hop(x))
    k_hop<<<NBATCH,256>>>((const float4*)x, (float4*)p_tmp);
    k_hop<<<NBATCH,256>>>((const float4*)p_tmp, (float4*)p_xq);

    // f1 = att(x, x_q, W[0]); f2 = att(x, qt, W[1])
    launch_attention(0, x, p_xq, p_qt, Wk, W1, W2, W3, p_a, p_h0, p_h1, p_h2, p_logit, p_f);

    // edge softmax -> S, agg
    k_edge<<<NBATCH,256>>>(x);

    // x_c = mean_h lrelu(x + agg @ lin_W[h])
    k_sgemm<<<dim3(2,64,2),256>>>(p_agg, linW, p_P, NNODES, HD, HD,
                                  0LL, (long long)HD*HD, (long long)NNODES*HD, 0);
    k_xc<<<(NNODES*HD)/256,256>>>(x);

    // x_q2 = hop(hop(x_c))
    k_hop<<<NBATCH,256>>>((const float4*)p_xc, (float4*)p_tmp);
    k_hop<<<NBATCH,256>>>((const float4*)p_tmp, (float4*)p_xq);

    // g1 = att(x_c, x_q2, W[2]); g2 = att(x_c, qt, W[3])
    launch_attention(2, p_xc, p_xq, p_qt, Wk, W1, W2, W3, p_a, p_h0, p_h1, p_h2, p_logit, p_f);

    // cluster_score = softmax_batch(g1+g2)
    k_sumpair<<<NNODES/256,256>>>();
    k_softmax64<<<NBATCH,64>>>(p_logit, p_score);

    // top-k, outputs
    k_topk<<<NBATCH,64>>>(out);
    k_xout<<<(NK*HD)/256,256>>>(x, out);
    cudaMemsetAsync(out + OFF_A2, 0, (size_t)NK*NK*sizeof(float));
    k_A2<<<NBATCH,256>>>(out);
}